// round 12
// baseline (speedup 1.0000x reference)
#include <cuda_runtime.h>
#include <cuda_bf16.h>

#define T_DATA 4096
#define SUB 1024
#define WPB 8   // warps per block; grid = SUB/WPB = 128 blocks
#define TS ((size_t)T_DATA * SUB)

__device__ __forceinline__ float tanh_(float x) {
    float y; asm("tanh.approx.f32 %0, %1;" : "=f"(y) : "f"(x)); return y;
}

// One warp per sub-unit; 8 units per block. 64-slot systolic ring in accA/accB
// (h-domain: 0.5*X_in). sigmoid(x) = 0.5 + 0.5*tanh(x/2); kern[0]==0 so Z_t
// depends on Z_{t-2} -> steps processed in PAIRS, chains interleaved.
// Modulo schedule per iteration (pair i):
//   T1(i): reinit slots (i-1)&63 and i; scatter Zb=Z_{i-1} (taps s-i);
//          shfl slots i+2 (Pa') and i+3 (Pb') for the NEXT iteration's head
//   head(i): F0/F1 tanh chains using Pa/Pb shfl'd in the PREVIOUS iteration
//            (full-iteration slack -> SHFL latency completely hidden)
//   T2(i): scatter Z0=Z_i (taps s-i-1)
// Missing-tap bookkeeping: Pa misses j<=1 (head adds k1*Za), Pb misses j<=2
// (head adds k1*Zb + k2*Za). Scatters into already-shfl'd slots are dead
// writes (slot is reinitialized before its next shfl) -> no double counting,
// including across chunk boundaries. I/O block-cooperative & coalesced.
__global__ __launch_bounds__(WPB*32, 1)
void leaf_kernel(const float* __restrict__ S_conv,
                 const float* __restrict__ up_mu_Z,
                 const float* __restrict__ noise,
                 const float* __restrict__ W_sub,
                 const float* __restrict__ theta_syn,
                 const float* __restrict__ theta_spike,
                 const float* __restrict__ W_spike,
                 const float* __restrict__ tau_hist,
                 const float* __restrict__ K_hist,
                 const float* __restrict__ delta_hist,
                 float* __restrict__ out)
{
    __shared__ __align__(16) float sh_kq[WPB][128];    // 0.5*kern, duplicated [j],[j+64]
    __shared__ __align__(16) float sh_a[WPB][66];      // 0.5*(s+th_syn) reinit values
    __shared__ __align__(16) float sh_c[WPB][66];      // 0.25*up + 0.5*n + c2const
    __shared__ __align__(16) float sh_u[64][WPB];      // 0.5*up (flush only)
    __shared__ __align__(16) float sh_v[32][WPB][4];   // {v10,v20,v11,v21} per pair

    const int tid  = threadIdx.x;
    const int lane = tid & 31;
    const int w    = tid >> 5;
    const int u0   = blockIdx.x * WPB;
    const int unit = u0 + w;
    const bool isl0 = (lane == 0);

    float* kq = sh_kq[w];

    // per-warp unit constants
    const float th_syn = theta_syn[unit];
    const float Wspk   = W_spike[unit];
    const float delta  = delta_hist[unit];
    const float q2     = 0.125f * Wspk;

    // per-thread column constants (staging + flush)
    const int  col    = tid & 7;
    const int  row0   = tid >> 3;        // 0..31
    const int  ucol   = u0 + col;
    const float thsyn_c = theta_syn[ucol];
    const float thspk_c = theta_spike[ucol];
    const float wspk_c  = W_spike[ucol];
    const float wsub_c  = W_sub[ucol];
    const float c2c_c   = 0.25f * thspk_c + 0.125f * wspk_c;
    const bool  oddrow  = (row0 & 1);

    // ---- taps: kq[j] = kq[j+64] = 0.5 * sum_b ttau*exp(-ttau)*K_b ; kq[0]==0 ----
    {
        const float K0 = K_hist[unit*4+0];
        const float K1 = K_hist[unit*4+1];
        const float K2 = K_hist[unit*4+2];
        const float K3 = K_hist[unit*4+3];
        const float it0 = __expf(-tau_hist[0]);
        const float it1 = __expf(-tau_hist[1]);
        const float it2 = __expf(-tau_hist[2]);
        const float it3 = __expf(-tau_hist[3]);
        #pragma unroll
        for (int rr = 0; rr < 2; rr++) {
            const int j = lane + rr*32;
            const float tt = fmaxf((float)j - delta, 0.0f);
            const float x0 = tt*it0, x1 = tt*it1, x2 = tt*it2, x3 = tt*it3;
            float s = x0*__expf(-x0)*K0;
            s = fmaf(x1*__expf(-x1), K1, s);
            s = fmaf(x2*__expf(-x2), K2, s);
            s = fmaf(x3*__expf(-x3), K3, s);
            kq[j]      = 0.5f * s;
            kq[j + 64] = 0.5f * s;
        }
    }

    // ---- ring init: slot t = 0.5*(s_t + th_syn), t = 0..63 ----
    float accA = 0.5f * (S_conv[(size_t)lane*SUB + unit] + th_syn);
    float accB = 0.5f * (S_conv[(size_t)(lane+32)*SUB + unit] + th_syn);
    __syncwarp();

    const float k1h = kq[1];
    const float k2h = kq[2];

    // ---- initial cooperative staging: c/u rows 0..63, a rows 64..127 ----
    #pragma unroll
    for (int rr = 0; rr < 2; rr++) {
        const int row = row0 + rr*32;
        const size_t idx = (size_t)row*SUB + ucol;
        const float up = up_mu_Z[idx];
        const float nz = noise[idx];
        sh_c[col][row] = fmaf(0.25f, up, fmaf(0.5f, nz, c2c_c));
        sh_u[row][col] = 0.5f * up;
        sh_a[col][row] = 0.5f * (S_conv[(size_t)(64+row)*SUB + ucol] + thsyn_c);
    }

    // pipeline bootstrap
    float Za = 0.0f, Zb = 0.0f;                         // Z_{-2}, Z_{-1}
    float Pa = __shfl_sync(0xffffffffu, accA, 0);       // slot 0 (pair 0 head)
    float Pb = __shfl_sync(0xffffffffu, accA, 1);       // slot 1
    float av_prev = __shfl_sync(0xffffffffu, accB, 31); // no-op reinit for slot 63 at pair 0

    __syncthreads();

    for (int base = 0; base < T_DATA; base += 64) {
        #pragma unroll
        for (int i = 0; i < 64; i += 2) {
            const float2 ccp = *(const float2*)&sh_c[w][i];
            const float2 avp = *(const float2*)&sh_a[w][i];
            const float kA0 = kq[64 + lane - i];
            const float kB0 = kq[96 + lane - i];
            const float kA1 = kq[63 + lane - i];
            const float kB1 = kq[95 + lane - i];

            // ---- T1: wheel advance with Zb = Z_{t0-1} ----
            {
                const int s = (i - 1) & 63;   // compile-time
                if (s < 32) { if (lane == s)      accA = av_prev; }
                else        { if (lane == s - 32) accB = av_prev; }
            }
            {
                if (i < 32) { if (lane == i)      accA = avp.x; }
                else        { if (lane == i - 32) accB = avp.x; }
            }
            accA = fmaf(kA0, Zb, accA);
            accB = fmaf(kB0, Zb, accB);
            float PaN, PbN;
            {
                const int nx = (i + 2) & 63;
                PaN = __shfl_sync(0xffffffffu, (nx & 32) ? accB : accA, nx & 31);
            }
            {
                const int nx = (i + 3) & 63;
                PbN = __shfl_sync(0xffffffffu, (nx & 32) ? accB : accA, nx & 31);
            }

            // ---- head: steps t0=base+i, t1=t0+1 (Pa/Pb from previous iteration) ----
            const float F0  = fmaf(k1h, Za, Pa);
            const float F1  = fmaf(k1h, Zb, fmaf(k2h, Za, Pb));
            const float v10 = tanh_(F0);
            const float v11 = tanh_(F1);
            const float g0  = fmaf(q2, v10, ccp.x);
            const float g1  = fmaf(q2, v11, ccp.y);
            const float v20 = tanh_(g0);
            const float v21 = tanh_(g1);
            const float Z0  = fmaf(0.5f, v20, 0.5f);
            const float Z1  = fmaf(0.5f, v21, 0.5f);
            if (isl0) {
                *(float4*)&sh_v[i>>1][w][0] = make_float4(v10, v20, v11, v21);
            }

            // ---- T2: scatter Z0 = Z_{t0} (post-shfl taps land in dead slots) ----
            accA = fmaf(kA1, Z0, accA);
            accB = fmaf(kB1, Z0, accB);

            // rotate pipeline registers
            Pa = PaN; Pb = PbN;
            Za = Z0;  Zb = Z1;  av_prev = avp.y;
        }

        __syncthreads();

        // ---- flush: coalesced outputs for this chunk ----
        #pragma unroll
        for (int rr = 0; rr < 2; rr++) {
            const int row = row0 + rr*32;
            const float4 vq = *(const float4*)&sh_v[row>>1][col][0];
            const float v1 = oddrow ? vq.z : vq.x;
            const float v2 = oddrow ? vq.w : vq.y;
            const float uu = sh_u[row][col];
            const float X  = fmaf(0.5f, v1, 0.5f);
            const float Z  = fmaf(0.5f, v2, 0.5f);
            const float Y  = X * wsub_c;
            const float dn = fmaf(X, wspk_c, thspk_c);
            const float mu = fmaf(0.5f, dn, uu);
            const size_t o = (size_t)(base + row)*SUB + ucol;
            out[o]        = Y;
            out[TS + o]   = Z;
            out[2*TS + o] = mu;
            out[3*TS + o] = dn;
        }

        // ---- stage next chunk (coalesced) ----
        const int nb = base + 64;
        if (nb < T_DATA) {
            #pragma unroll
            for (int rr = 0; rr < 2; rr++) {
                const int row = row0 + rr*32;
                const size_t idx = (size_t)(nb + row)*SUB + ucol;
                const float up = up_mu_Z[idx];
                const float nz = noise[idx];
                sh_c[col][row] = fmaf(0.25f, up, fmaf(0.5f, nz, c2c_c));
                sh_u[row][col] = 0.5f * up;
                const int ar = nb + 64 + row;
                sh_a[col][row] = (ar < T_DATA)
                    ? 0.5f * (S_conv[(size_t)ar*SUB + ucol] + thsyn_c) : 0.0f;
            }
        }
        __syncthreads();
    }
}

extern "C" void kernel_launch(void* const* d_in, const int* in_sizes, int n_in,
                              void* d_out, int out_size) {
    (void)in_sizes; (void)n_in; (void)out_size;
    leaf_kernel<<<SUB/WPB, WPB*32>>>(
        (const float*)d_in[0],  // S_conv
        (const float*)d_in[1],  // up_mu_Z
        (const float*)d_in[2],  // noise
        (const float*)d_in[3],  // W_sub
        (const float*)d_in[4],  // theta_syn
        (const float*)d_in[5],  // theta_spike
        (const float*)d_in[6],  // W_spike
        (const float*)d_in[7],  // tau_hist
        (const float*)d_in[8],  // K_hist
        (const float*)d_in[9],  // delta_hist
        (float*)d_out);
}